// round 8
// baseline (speedup 1.0000x reference)
#include <cuda_runtime.h>

#define HH 256
#define WW 256
#define NT 16
#define NB 8
#define NIMG (NB*NT)
#define HW (HH*WW)
#define SAMPLE_ELEMS (NT*HW)          // 1048576
#define WIN 11
#define PADW 5
#define SPLIT 2
#define SEG (HH/SPLIT)                // 128
#define NLOADS (SEG + 10)             // 138 row loads per segment
#define RED_BLKS 64
#define GRID1 (NB*RED_BLKS)           // 512
#define NPAIR (NIMG/2)                // 64
#define GRID2 (NPAIR*SPLIT)           // 128
#define SSIM_EPS 1e-6f
#define C1_ (1.0e-4f)
#define C2_ (9.0e-4f)
#define C3_ (4.5e-4f)

// canonical 11-tap sigma=1.5 gaussian
#define GW0 0.0010283799f
#define GW1 0.0075987583f
#define GW2 0.0360007723f
#define GW3 0.1093606947f
#define GW4 0.2130055329f
#define GW5 0.2660117190f

typedef unsigned long long u64;

// scratch (no allocations allowed)
__device__ float g_partial[5 * NB * RED_BLKS];   // stat-major: pmn,pmx,tmn,tmx,tsum
__device__ float g_params[NB * 4];               // mnt, invt, mnp, invp
__device__ float g_valid[NB];
__device__ float g_ssim[NB];
__device__ unsigned int g_cnt1;
__device__ unsigned int g_cnt2;

// ---- packed f32x2 helpers -------------------------------------------------
__device__ __forceinline__ u64 pk2(float x, float y) {
    u64 r; asm("mov.b64 %0,{%1,%2};" : "=l"(r) : "f"(x), "f"(y)); return r;
}
__device__ __forceinline__ void upk2(float& x, float& y, u64 v) {
    asm("mov.b64 {%0,%1},%2;" : "=f"(x), "=f"(y) : "l"(v));
}
__device__ __forceinline__ u64 fma2(u64 a, u64 b, u64 c) {
    u64 d; asm("fma.rn.f32x2 %0,%1,%2,%3;" : "=l"(d) : "l"(a), "l"(b), "l"(c)); return d;
}
__device__ __forceinline__ u64 mul2(u64 a, u64 b) {
    u64 d; asm("mul.rn.f32x2 %0,%1,%2;" : "=l"(d) : "l"(a), "l"(b)); return d;
}

// ---------------------------------------------------------------------------
// Kernel 1: per-sample min/max of pred & tgt, sum of tgt (64 blocks/sample),
//           with fused finalize in the last-arriving block.
// ---------------------------------------------------------------------------
__global__ __launch_bounds__(256) void reduce_kernel(const float* __restrict__ pred,
                                                     const float* __restrict__ tgt) {
    int b   = blockIdx.x >> 6;
    int blk = blockIdx.x & 63;
    int tid = threadIdx.x;

    const float4* p4 = (const float4*)(pred + (size_t)b * SAMPLE_ELEMS + (size_t)blk * 16384);
    const float4* t4 = (const float4*)(tgt  + (size_t)b * SAMPLE_ELEMS + (size_t)blk * 16384);

    float pmn = 1e30f, pmx = -1e30f, tmn = 1e30f, tmx = -1e30f, ts = 0.f;
    #pragma unroll 4
    for (int i = tid; i < 4096; i += 256) {
        float4 a = p4[i];
        pmn = fminf(pmn, fminf(fminf(a.x, a.y), fminf(a.z, a.w)));
        pmx = fmaxf(pmx, fmaxf(fmaxf(a.x, a.y), fmaxf(a.z, a.w)));
        float4 c = t4[i];
        tmn = fminf(tmn, fminf(fminf(c.x, c.y), fminf(c.z, c.w)));
        tmx = fmaxf(tmx, fmaxf(fmaxf(c.x, c.y), fmaxf(c.z, c.w)));
        ts += (c.x + c.y) + (c.z + c.w);
    }
    #pragma unroll
    for (int o = 16; o; o >>= 1) {
        pmn = fminf(pmn, __shfl_xor_sync(~0u, pmn, o));
        pmx = fmaxf(pmx, __shfl_xor_sync(~0u, pmx, o));
        tmn = fminf(tmn, __shfl_xor_sync(~0u, tmn, o));
        tmx = fmaxf(tmx, __shfl_xor_sync(~0u, tmx, o));
        ts += __shfl_xor_sync(~0u, ts, o);
    }
    __shared__ float sm[8 * 5];
    int wid = tid >> 5;
    if ((tid & 31) == 0) {
        sm[wid * 5 + 0] = pmn; sm[wid * 5 + 1] = pmx;
        sm[wid * 5 + 2] = tmn; sm[wid * 5 + 3] = tmx;
        sm[wid * 5 + 4] = ts;
    }
    __syncthreads();
    if (tid == 0) {
        float a0 = sm[0], a1 = sm[1], a2 = sm[2], a3 = sm[3], a4 = sm[4];
        #pragma unroll
        for (int w = 1; w < 8; ++w) {
            a0 = fminf(a0, sm[w * 5 + 0]);
            a1 = fmaxf(a1, sm[w * 5 + 1]);
            a2 = fminf(a2, sm[w * 5 + 2]);
            a3 = fmaxf(a3, sm[w * 5 + 3]);
            a4 += sm[w * 5 + 4];
        }
        int base = b * RED_BLKS + blk;
        g_partial[0 * GRID1 + base] = a0;
        g_partial[1 * GRID1 + base] = a1;
        g_partial[2 * GRID1 + base] = a2;
        g_partial[3 * GRID1 + base] = a3;
        g_partial[4 * GRID1 + base] = a4;
        __threadfence();
    }
    __syncthreads();

    // ---- fused finalize: last block folds partials -> params ----
    __shared__ int amLast;
    if (tid == 0) amLast = (atomicAdd(&g_cnt1, 1u) == GRID1 - 1);
    __syncthreads();
    if (!amLast) return;

    // warp w handles sample b=w (8 warps)
    int wb  = tid >> 5;
    int lid = tid & 31;
    {
        int i0 = wb * RED_BLKS + lid;
        int i1 = i0 + 32;
        float a = fminf(g_partial[0 * GRID1 + i0], g_partial[0 * GRID1 + i1]);
        float c = fmaxf(g_partial[1 * GRID1 + i0], g_partial[1 * GRID1 + i1]);
        float d = fminf(g_partial[2 * GRID1 + i0], g_partial[2 * GRID1 + i1]);
        float e = fmaxf(g_partial[3 * GRID1 + i0], g_partial[3 * GRID1 + i1]);
        float s =       g_partial[4 * GRID1 + i0] + g_partial[4 * GRID1 + i1];
        #pragma unroll
        for (int o = 16; o; o >>= 1) {
            a = fminf(a, __shfl_xor_sync(~0u, a, o));
            c = fmaxf(c, __shfl_xor_sync(~0u, c, o));
            d = fminf(d, __shfl_xor_sync(~0u, d, o));
            e = fmaxf(e, __shfl_xor_sync(~0u, e, o));
            s += __shfl_xor_sync(~0u, s, o);
        }
        if (lid == 0) {
            float invp = 1.0f / fmaxf(c - a, SSIM_EPS);
            float invt = 1.0f / fmaxf(e - d, SSIM_EPS);
            g_params[wb * 4 + 0] = d;
            g_params[wb * 4 + 1] = invt;
            g_params[wb * 4 + 2] = a;
            g_params[wb * 4 + 3] = invp;
            g_valid[wb] = (s != 0.0f) ? 1.0f : 0.0f;
            g_ssim[wb]  = 0.0f;
        }
    }
    if (tid == 0) g_cnt1 = 0;   // reset for next graph replay
}

// ---------------------------------------------------------------------------
// Kernel 2: fused normalize + separable 11x11 gauss conv (5 fields) + SSIM.
// Packed f32x2 across a FRAME PAIR (same sample => same norm params).
// One thread per column; 11-deep compile-time register ring of packed values;
// rotating 2-slot smem row buffer (u64 entries), register prefetch of next row.
// Last block computes the final scalar loss.
// ---------------------------------------------------------------------------
__global__ __launch_bounds__(256, 1) void conv_kernel(const float* __restrict__ pred,
                                                      const float* __restrict__ tgt,
                                                      float* __restrict__ out, int out_size) {
    const float w[WIN] = {GW0, GW1, GW2, GW3, GW4, GW5, GW4, GW3, GW2, GW1, GW0};

    int pair = blockIdx.x >> 1;       // frame pair (2*pair, 2*pair+1)
    int seg  = blockIdx.x & 1;
    int nA   = pair * 2;
    int b    = nA >> 4;
    int tid  = threadIdx.x;           // column x

    float mnt  = g_params[b * 4 + 0];
    float invt = g_params[b * 4 + 1];
    float mnp  = g_params[b * 4 + 2];
    float invp = g_params[b * 4 + 3];
    float ct_c = -mnt * invt;         // tn = fma(t, invt, ct_c)
    float cp_c = -mnp * invp;

    // packed weights (built once, live in registers)
    u64 w2[WIN];
    #pragma unroll
    for (int k = 0; k < WIN; ++k) w2[k] = pk2(w[k], w[k]);

    // rotating row buffers: [slot][col], u64 = {frameA, frameB} packed.
    __shared__ u64 s_t[2][WW + 2 * PADW + 2];
    __shared__ u64 s_p[2][WW + 2 * PADW + 2];
    if (tid < PADW) {
        s_t[0][tid] = 0ull; s_t[1][tid] = 0ull;
        s_p[0][tid] = 0ull; s_p[1][tid] = 0ull;
        s_t[0][PADW + WW + tid] = 0ull; s_t[1][PADW + WW + tid] = 0ull;
        s_p[0][PADW + WW + tid] = 0ull; s_p[1][PADW + WW + tid] = 0ull;
    }
    __syncthreads();

    int r0 = seg * SEG;
    const float* tb = tgt  + (size_t)nA * HW;   // frame B at +HW
    const float* pb = pred + (size_t)nA * HW;

    u64 rt[WIN], rp[WIN], rtt[WIN], rpp[WIN], rtp[WIN];
    float acc = 0.f;

    // prefetch row i=0
    u64 cur_t = 0ull, cur_p = 0ull;
    {
        int y = r0 - PADW;
        if (y >= 0) {   // y < HH always for i=0
            int idx = y * WW + tid;
            cur_t = pk2(fmaf(tb[idx], invt, ct_c), fmaf(tb[idx + HW], invt, ct_c));
            cur_p = pk2(fmaf(pb[idx], invp, cp_c), fmaf(pb[idx + HW], invp, cp_c));
        }
    }

    #pragma unroll 1
    for (int base = 0; base < 143; base += 11) {
        #pragma unroll
        for (int u = 0; u < 11; ++u) {
            int i = base + u;                 // row index being processed
            int y = r0 - PADW + i;
            bool live  = (i < NLOADS);
            bool inimg = live && (y >= 0) && (y < HH);
            int slot = i & 1;

            if (inimg) {
                s_t[slot][PADW + tid] = cur_t;
                s_p[slot][PADW + tid] = cur_p;
            }
            __syncthreads();

            // prefetch row i+1 (a full iteration of latency cover)
            {
                int y2 = y + 1;
                if ((i + 1) < NLOADS && y2 >= 0 && y2 < HH) {
                    int idx = y2 * WW + tid;
                    cur_t = pk2(fmaf(tb[idx], invt, ct_c), fmaf(tb[idx + HW], invt, ct_c));
                    cur_p = pk2(fmaf(pb[idx], invp, cp_c), fmaf(pb[idx + HW], invp, cp_c));
                }
            }

            // horizontal conv of 5 fields, packed over the frame pair
            u64 at = 0ull, ap = 0ull, att = 0ull, app = 0ull, atp = 0ull;
            if (inimg) {
                const u64* rowt = &s_t[slot][tid];
                const u64* rowp = &s_p[slot][tid];
                #pragma unroll
                for (int k = 0; k < WIN; ++k) {
                    u64 mt = rowt[k];           // LDS.64
                    u64 mp = rowp[k];           // LDS.64
                    u64 wk = w2[k];
                    at  = fma2(wk, mt, at);
                    ap  = fma2(wk, mp, ap);
                    u64 wt = mul2(wk, mt);
                    u64 wp = mul2(wk, mp);
                    att = fma2(wt, mt, att);
                    app = fma2(wp, mp, app);
                    atp = fma2(wt, mp, atp);
                }
            }
            rt[u] = at; rp[u] = ap; rtt[u] = att; rpp[u] = app; rtp[u] = atp;

            if (i >= 10 && live) {
                // vertical conv (output row oy = r0 + i - 10), packed
                u64 ct = 0ull, cp = 0ull, ctt = 0ull, cpp = 0ull, ctp = 0ull;
                #pragma unroll
                for (int s = 0; s < 11; ++s) {
                    int d = (s - u + 10) % 11;       // compile-time per (u,s)
                    u64 wd = w2[d];
                    ct  = fma2(wd, rt[s],  ct);
                    cp  = fma2(wd, rp[s],  cp);
                    ctt = fma2(wd, rtt[s], ctt);
                    cpp = fma2(wd, rpp[s], cpp);
                    ctp = fma2(wd, rtp[s], ctp);
                }
                // scalar SSIM epilogue per lane
                float m1a, m1b, m2a, m2b, ea, eb, fa, fb, ga, gb;
                upk2(m1a, m1b, ct);  upk2(m2a, m2b, cp);
                upk2(ea, eb, ctt);   upk2(fa, fb, cpp);  upk2(ga, gb, ctp);
                #pragma unroll
                for (int l = 0; l < 2; ++l) {
                    float mu1 = l ? m1b : m1a;
                    float mu2 = l ? m2b : m2a;
                    float ee  = l ? eb : ea;
                    float ff  = l ? fb : fa;
                    float gg  = l ? gb : ga;
                    float mu1s = mu1 * mu1;
                    float mu2s = mu2 * mu2;
                    float mu12 = mu1 * mu2;
                    float s1   = fmaxf(ee - mu1s, SSIM_EPS);
                    float s2   = fmaxf(ff - mu2s, SSIM_EPS);
                    float s12  = gg - mu12;
                    float root = sqrtf(s1 * s2);
                    float lum  = __fdividef(2.0f * mu12 + C1_, mu1s + mu2s + C1_);
                    float con  = __fdividef(2.0f * root + C2_, s1 + s2 + C2_);
                    float str  = __fdividef(s12 + C3_, root + C3_);
                    acc += lum * con * str;
                }
            }
        }
    }

    // block reduce + single atomic per block (both frames share b)
    #pragma unroll
    for (int o = 16; o; o >>= 1) acc += __shfl_xor_sync(~0u, acc, o);
    __shared__ float red[8];
    if ((tid & 31) == 0) red[tid >> 5] = acc;
    __syncthreads();
    __shared__ int amLast;
    if (tid == 0) {
        float t = red[0];
        #pragma unroll
        for (int ww = 1; ww < 8; ++ww) t += red[ww];
        atomicAdd(&g_ssim[b], t);
        __threadfence();
        amLast = (atomicAdd(&g_cnt2, 1u) == GRID2 - 1);
    }
    __syncthreads();
    if (!amLast) return;

    // ---- fused final loss (last block) ----
    if (tid < 32) {
        float v = 0.f, s = 0.f;
        if (tid < NB) {
            v = g_valid[tid];
            s = (1.0f - g_ssim[tid] * (1.0f / (float)SAMPLE_ELEMS)) * v;
        }
        #pragma unroll
        for (int o = 16; o; o >>= 1) {
            s += __shfl_xor_sync(~0u, s, o);
            v += __shfl_xor_sync(~0u, v, o);
        }
        if (tid == 0) {
            float loss = s / fmaxf(v, 1.0f);
            for (int i = 0; i < out_size; ++i) out[i] = loss;
            g_cnt2 = 0;   // reset for next graph replay
        }
    }
}

extern "C" void kernel_launch(void* const* d_in, const int* in_sizes, int n_in,
                              void* d_out, int out_size) {
    const float* pred = (const float*)d_in[0];
    const float* tgt  = (const float*)d_in[1];
    float* out = (float*)d_out;

    reduce_kernel<<<GRID1, 256>>>(pred, tgt);
    conv_kernel<<<GRID2, 256>>>(pred, tgt, out, out_size);
}

// round 9
// speedup vs baseline: 1.0985x; 1.0985x over previous
#include <cuda_runtime.h>

#define HH 256
#define WW 256
#define NT 16
#define NB 8
#define NIMG (NB*NT)
#define HW (HH*WW)
#define SAMPLE_ELEMS (NT*HW)          // 1048576
#define WIN 11
#define PADW 5
#define SPLIT 2
#define SEG (HH/SPLIT)                // 128
#define NLOADS (SEG + 10)             // 138 row loads per segment
#define BW 128                        // columns per block
#define RED_BLKS 64
#define GRID1 (NB*RED_BLKS)           // 512
#define GRID2 (NIMG*SPLIT*2)          // 512 (frames x segs x col-halves)
#define SSIM_EPS 1e-6f
#define C1_ (1.0e-4f)
#define C2_ (9.0e-4f)
#define C3_ (4.5e-4f)

// canonical 11-tap sigma=1.5 gaussian
#define GW0 0.0010283799f
#define GW1 0.0075987583f
#define GW2 0.0360007723f
#define GW3 0.1093606947f
#define GW4 0.2130055329f
#define GW5 0.2660117190f

typedef unsigned long long u64;

// scratch (no allocations allowed)
__device__ float g_partial[5 * GRID1];   // stat-major: pmn,pmx,tmn,tmx,tsum
__device__ float g_params[NB * 4];       // mnt, invt, mnp, invp
__device__ float g_valid[NB];
__device__ float g_ssim[NB];
__device__ unsigned int g_cnt1;
__device__ unsigned int g_cnt2;

// ---- packed f32x2 helpers (u64 = register pair; pk/upk are free) ----------
__device__ __forceinline__ u64 pk2(float x, float y) {
    u64 r; asm("mov.b64 %0,{%1,%2};" : "=l"(r) : "f"(x), "f"(y)); return r;
}
__device__ __forceinline__ void upk2(float& x, float& y, u64 v) {
    asm("mov.b64 {%0,%1},%2;" : "=f"(x), "=f"(y) : "l"(v));
}
__device__ __forceinline__ u64 fma2(u64 a, u64 b, u64 c) {
    u64 d; asm("fma.rn.f32x2 %0,%1,%2,%3;" : "=l"(d) : "l"(a), "l"(b), "l"(c)); return d;
}
__device__ __forceinline__ u64 mul2(u64 a, u64 b) {
    u64 d; asm("mul.rn.f32x2 %0,%1,%2;" : "=l"(d) : "l"(a), "l"(b)); return d;
}

// ---------------------------------------------------------------------------
// Kernel 1: per-sample min/max of pred & tgt, sum of tgt (64 blocks/sample),
//           fused finalize in the last-arriving block.
// ---------------------------------------------------------------------------
__global__ __launch_bounds__(256) void reduce_kernel(const float* __restrict__ pred,
                                                     const float* __restrict__ tgt) {
    int b   = blockIdx.x >> 6;
    int blk = blockIdx.x & 63;
    int tid = threadIdx.x;

    const float4* p4 = (const float4*)(pred + (size_t)b * SAMPLE_ELEMS + (size_t)blk * 16384);
    const float4* t4 = (const float4*)(tgt  + (size_t)b * SAMPLE_ELEMS + (size_t)blk * 16384);

    float pmn = 1e30f, pmx = -1e30f, tmn = 1e30f, tmx = -1e30f, ts = 0.f;
    #pragma unroll 4
    for (int i = tid; i < 4096; i += 256) {
        float4 a = p4[i];
        pmn = fminf(pmn, fminf(fminf(a.x, a.y), fminf(a.z, a.w)));
        pmx = fmaxf(pmx, fmaxf(fmaxf(a.x, a.y), fmaxf(a.z, a.w)));
        float4 c = t4[i];
        tmn = fminf(tmn, fminf(fminf(c.x, c.y), fminf(c.z, c.w)));
        tmx = fmaxf(tmx, fmaxf(fmaxf(c.x, c.y), fmaxf(c.z, c.w)));
        ts += (c.x + c.y) + (c.z + c.w);
    }
    #pragma unroll
    for (int o = 16; o; o >>= 1) {
        pmn = fminf(pmn, __shfl_xor_sync(~0u, pmn, o));
        pmx = fmaxf(pmx, __shfl_xor_sync(~0u, pmx, o));
        tmn = fminf(tmn, __shfl_xor_sync(~0u, tmn, o));
        tmx = fmaxf(tmx, __shfl_xor_sync(~0u, tmx, o));
        ts += __shfl_xor_sync(~0u, ts, o);
    }
    __shared__ float sm[8 * 5];
    int wid = tid >> 5;
    if ((tid & 31) == 0) {
        sm[wid * 5 + 0] = pmn; sm[wid * 5 + 1] = pmx;
        sm[wid * 5 + 2] = tmn; sm[wid * 5 + 3] = tmx;
        sm[wid * 5 + 4] = ts;
    }
    __syncthreads();
    if (tid == 0) {
        float a0 = sm[0], a1 = sm[1], a2 = sm[2], a3 = sm[3], a4 = sm[4];
        #pragma unroll
        for (int w = 1; w < 8; ++w) {
            a0 = fminf(a0, sm[w * 5 + 0]);
            a1 = fmaxf(a1, sm[w * 5 + 1]);
            a2 = fminf(a2, sm[w * 5 + 2]);
            a3 = fmaxf(a3, sm[w * 5 + 3]);
            a4 += sm[w * 5 + 4];
        }
        int base = b * RED_BLKS + blk;
        g_partial[0 * GRID1 + base] = a0;
        g_partial[1 * GRID1 + base] = a1;
        g_partial[2 * GRID1 + base] = a2;
        g_partial[3 * GRID1 + base] = a3;
        g_partial[4 * GRID1 + base] = a4;
        __threadfence();
    }
    __syncthreads();

    __shared__ int amLast;
    if (tid == 0) amLast = (atomicAdd(&g_cnt1, 1u) == GRID1 - 1);
    __syncthreads();
    if (!amLast) return;

    int wb  = tid >> 5;   // warp wb -> sample wb
    int lid = tid & 31;
    {
        int i0 = wb * RED_BLKS + lid;
        int i1 = i0 + 32;
        float a = fminf(g_partial[0 * GRID1 + i0], g_partial[0 * GRID1 + i1]);
        float c = fmaxf(g_partial[1 * GRID1 + i0], g_partial[1 * GRID1 + i1]);
        float d = fminf(g_partial[2 * GRID1 + i0], g_partial[2 * GRID1 + i1]);
        float e = fmaxf(g_partial[3 * GRID1 + i0], g_partial[3 * GRID1 + i1]);
        float s =       g_partial[4 * GRID1 + i0] + g_partial[4 * GRID1 + i1];
        #pragma unroll
        for (int o = 16; o; o >>= 1) {
            a = fminf(a, __shfl_xor_sync(~0u, a, o));
            c = fmaxf(c, __shfl_xor_sync(~0u, c, o));
            d = fminf(d, __shfl_xor_sync(~0u, d, o));
            e = fmaxf(e, __shfl_xor_sync(~0u, e, o));
            s += __shfl_xor_sync(~0u, s, o);
        }
        if (lid == 0) {
            float invp = 1.0f / fmaxf(c - a, SSIM_EPS);
            float invt = 1.0f / fmaxf(e - d, SSIM_EPS);
            g_params[wb * 4 + 0] = d;
            g_params[wb * 4 + 1] = invt;
            g_params[wb * 4 + 2] = a;
            g_params[wb * 4 + 3] = invp;
            g_valid[wb] = (s != 0.0f) ? 1.0f : 0.0f;
            g_ssim[wb]  = 0.0f;
        }
    }
    if (tid == 0) g_cnt1 = 0;   // reset for next graph replay
}

// ---------------------------------------------------------------------------
// Kernel 2: fused normalize + separable conv + SSIM.
// FIELD-packed f32x2: {t,p} pairs flow through the whole pipeline.
// 128-thread blocks (half image width + halo), 4 blocks/SM for latency hiding.
// One thread per output column; 11-deep compile-time ring (2 u64 + 1 float per
// row). Rotating 2-slot smem row buffer, register prefetch of next row.
// Last block computes the final scalar loss.
// ---------------------------------------------------------------------------
__global__ __launch_bounds__(BW, 4) void conv_kernel(const float* __restrict__ pred,
                                                     const float* __restrict__ tgt,
                                                     float* __restrict__ out, int out_size) {
    const float w[WIN] = {GW0, GW1, GW2, GW3, GW4, GW5, GW4, GW3, GW2, GW1, GW0};

    int blk  = blockIdx.x;
    int half = blk & 1;               // column half
    int seg  = (blk >> 1) & 1;        // row segment
    int n    = blk >> 2;              // frame
    int b    = n >> 4;
    int tid  = threadIdx.x;
    int c0   = half * BW;

    float mnt  = g_params[b * 4 + 0];
    float invt = g_params[b * 4 + 1];
    float mnp  = g_params[b * 4 + 2];
    float invp = g_params[b * 4 + 3];
    float ctc = -mnt * invt;          // tn = fma(t, invt, ctc)
    float cpc = -mnp * invp;

    u64 w2[WIN];
    #pragma unroll
    for (int k = 0; k < WIN; ++k) w2[k] = pk2(w[k], w[k]);

    // rotating row buffers: entries {t_norm, p_norm}; positions 0..137 cover
    // global columns [c0-5, c0+132].
    __shared__ u64 sb[2][BW + 2 * PADW + 6];

    int r0 = seg * SEG;
    const float* tb = tgt  + (size_t)n * HW;
    const float* pb = pred + (size_t)n * HW;

    // prefetch row i=0 (y = r0 - 5; only valid for seg==1 when y>=0... r0=0 -> y=-5 invalid)
    u64 cur0 = 0ull, cur1 = 0ull;
    int gcol  = c0 - PADW + tid;            // position tid
    int gcol2 = gcol + BW;                  // position tid+BW (only tid<10)
    {
        int y = r0 - PADW;
        if (y >= 0) {
            if (gcol >= 0 && gcol < WW) {
                int idx = y * WW + gcol;
                cur0 = pk2(fmaf(tb[idx], invt, ctc), fmaf(pb[idx], invp, cpc));
            }
            if (tid < 10 && gcol2 < WW) {
                int idx = y * WW + gcol2;
                cur1 = pk2(fmaf(tb[idx], invt, ctc), fmaf(pb[idx], invp, cpc));
            }
        }
    }

    u64 rmu[WIN], rsq[WIN];
    float rtp[WIN];
    float acc = 0.f;

    #pragma unroll 1
    for (int base = 0; base < 143; base += 11) {
        #pragma unroll
        for (int u = 0; u < 11; ++u) {
            int i = base + u;                 // row index
            int y = r0 - PADW + i;
            bool live  = (i < NLOADS);
            bool inimg = live && (y >= 0) && (y < HH);
            int slot = i & 1;

            sb[slot][tid] = cur0;
            if (tid < 10) sb[slot][BW + tid] = cur1;
            __syncthreads();

            // prefetch row i+1 (full iteration of latency cover)
            {
                int y2 = y + 1;
                cur0 = 0ull; cur1 = 0ull;
                if ((i + 1) < NLOADS && y2 >= 0 && y2 < HH) {
                    if (gcol >= 0 && gcol < WW) {
                        int idx = y2 * WW + gcol;
                        cur0 = pk2(fmaf(tb[idx], invt, ctc), fmaf(pb[idx], invp, cpc));
                    }
                    if (tid < 10 && gcol2 < WW) {
                        int idx = y2 * WW + gcol2;
                        cur1 = pk2(fmaf(tb[idx], invt, ctc), fmaf(pb[idx], invp, cpc));
                    }
                }
            }

            // horizontal conv, field-packed: mu={Σwt,Σwp}, sq={Σwt²,Σwp²}, tp=Σwtp
            u64 mu = 0ull, sq = 0ull;
            float tp = 0.f;
            if (inimg) {
                const u64* row = &sb[slot][tid];
                #pragma unroll
                for (int k = 0; k < WIN; ++k) {
                    u64 m  = row[k];            // LDS.64 {t,p}
                    u64 wk = w2[k];
                    mu = fma2(wk, m, mu);
                    u64 wm = mul2(wk, m);       // {w t, w p}
                    sq = fma2(wm, m, sq);
                    float wt_, wp_; upk2(wt_, wp_, wm);   // free
                    float mt_, mp_; upk2(mt_, mp_, m);    // free
                    tp = fmaf(wt_, mp_, tp);
                }
            }
            rmu[u] = mu; rsq[u] = sq; rtp[u] = tp;

            if (i >= 10 && live) {
                // vertical conv (output row oy = r0 + i - 10)
                u64 cmu = 0ull, csq = 0ull;
                float ctp = 0.f;
                #pragma unroll
                for (int s = 0; s < 11; ++s) {
                    int d = (s - u + 10) % 11;       // compile-time per (u,s)
                    u64 wd = w2[d];
                    cmu = fma2(wd, rmu[s], cmu);
                    csq = fma2(wd, rsq[s], csq);
                    ctp = fmaf(w[d], rtp[s], ctp);
                }
                float mu1, mu2, ett, epp;
                upk2(mu1, mu2, cmu);
                upk2(ett, epp, csq);
                float mu1s = mu1 * mu1;
                float mu2s = mu2 * mu2;
                float mu12 = mu1 * mu2;
                float s1   = fmaxf(ett - mu1s, SSIM_EPS);
                float s2   = fmaxf(epp - mu2s, SSIM_EPS);
                float s12  = ctp - mu12;
                float root = sqrtf(s1 * s2);
                float num  = (2.0f * mu12 + C1_) * (2.0f * root + C2_) * (s12 + C3_);
                float den  = (mu1s + mu2s + C1_) * (s1 + s2 + C2_) * (root + C3_);
                acc += __fdividef(num, den);
            }
        }
    }

    // block reduce (4 warps) + single atomic
    #pragma unroll
    for (int o = 16; o; o >>= 1) acc += __shfl_xor_sync(~0u, acc, o);
    __shared__ float red[4];
    if ((tid & 31) == 0) red[tid >> 5] = acc;
    __syncthreads();
    __shared__ int amLast;
    if (tid == 0) {
        float t = red[0] + red[1] + red[2] + red[3];
        atomicAdd(&g_ssim[b], t);
        __threadfence();
        amLast = (atomicAdd(&g_cnt2, 1u) == GRID2 - 1);
    }
    __syncthreads();
    if (!amLast) return;

    // ---- fused final loss (last block) ----
    if (tid < 32) {
        float v = 0.f, s = 0.f;
        if (tid < NB) {
            v = g_valid[tid];
            s = (1.0f - g_ssim[tid] * (1.0f / (float)SAMPLE_ELEMS)) * v;
        }
        #pragma unroll
        for (int o = 16; o; o >>= 1) {
            s += __shfl_xor_sync(~0u, s, o);
            v += __shfl_xor_sync(~0u, v, o);
        }
        if (tid == 0) {
            float loss = s / fmaxf(v, 1.0f);
            for (int i = 0; i < out_size; ++i) out[i] = loss;
            g_cnt2 = 0;   // reset for next graph replay
        }
    }
}

extern "C" void kernel_launch(void* const* d_in, const int* in_sizes, int n_in,
                              void* d_out, int out_size) {
    const float* pred = (const float*)d_in[0];
    const float* tgt  = (const float*)d_in[1];
    float* out = (float*)d_out;

    reduce_kernel<<<GRID1, 256>>>(pred, tgt);
    conv_kernel<<<GRID2, BW>>>(pred, tgt, out, out_size);
}